// round 4
// baseline (speedup 1.0000x reference)
#include <cuda_runtime.h>
#include <math.h>

#define N_NODES 100000
#define C 128
#define TILE_NODES 32
#define LAYER_THREADS 256
// smem: Wl(128*128) + Wr(128*128) + agg_tile(32*128) + x_tile(32*128) floats
#define SMEM_FLOATS (2 * C * C + 2 * TILE_NODES * C)
#define SMEM_BYTES (SMEM_FLOATS * 4)

// Scratch (allocation-free rule: __device__ globals)
__device__ float g_agg[(size_t)N_NODES * C];
__device__ float g_h1[(size_t)N_NODES * C];
__device__ float g_deg[N_NODES];

// ---------------------------------------------------------------------------
// Zero scratch
// ---------------------------------------------------------------------------
__global__ void zero_kernel(float* __restrict__ p, size_t n4) {
    float4* p4 = (float4*)p;
    float4 z = make_float4(0.f, 0.f, 0.f, 0.f);
    for (size_t i = (size_t)blockIdx.x * blockDim.x + threadIdx.x; i < n4;
         i += (size_t)gridDim.x * blockDim.x)
        p4[i] = z;
}

__global__ void zero_scalar_kernel(float* __restrict__ p, int n) {
    int i = blockIdx.x * blockDim.x + threadIdx.x;
    if (i < n) p[i] = 0.f;
}

// ---------------------------------------------------------------------------
// Scatter: accum[dst] += feat[src], deg[dst] += 1. One warp per edge.
// Lane l owns floats [4l, 4l+4) of the 128-wide row. Indices are int32.
// ---------------------------------------------------------------------------
__global__ void scatter_kernel(const float* __restrict__ feat,
                               const int* __restrict__ src,
                               const int* __restrict__ dst,
                               float* __restrict__ accum,
                               float* __restrict__ deg,
                               int E, int add_deg) {
    int warp = (blockIdx.x * blockDim.x + threadIdx.x) >> 5;
    int lane = threadIdx.x & 31;
    if (warp >= E) return;
    int s = src[warp];
    int d = dst[warp];
    float4 v = ((const float4*)(feat + (size_t)s * C))[lane];
    float* a = accum + (size_t)d * C + lane * 4;
    atomicAdd(a + 0, v.x);
    atomicAdd(a + 1, v.y);
    atomicAdd(a + 2, v.z);
    atomicAdd(a + 3, v.w);
    if (add_deg && lane == 0) atomicAdd(deg + d, 1.0f);
}

// ---------------------------------------------------------------------------
// Fused SAGE layer:
//   h[i] = relu( (agg_sum[i]/max(deg[i],1)) @ Wl + in[i] @ Wr + b )
// If FC: instead of storing h, compute sigmoid(h @ Wfc + bfc) -> out_fc[i].
//
// Persistent blocks. 256 threads, 32-node tiles, 4 nodes x 4 outs per thread.
// Both weight matrices resident in shared memory for the whole kernel.
// 100000 / 32 = 3125 tiles exactly.
// ---------------------------------------------------------------------------
template <bool FC>
__global__ void layer_kernel(const float* __restrict__ in_feat,
                             const float* __restrict__ agg_sum,
                             const float* __restrict__ deg,
                             const float* __restrict__ Wl,
                             const float* __restrict__ Wr,
                             const float* __restrict__ bias,
                             float* __restrict__ out_h,
                             const float* __restrict__ Wfc,
                             const float* __restrict__ bfc,
                             float* __restrict__ out_fc,
                             int n_nodes) {
    extern __shared__ float smem[];
    float* Wls = smem;                 // [128][128]
    float* Wrs = Wls + C * C;          // [128][128]
    float* as_ = Wrs + C * C;          // [32][128] normalized agg
    float* xs_ = as_ + TILE_NODES * C; // [32][128] input feats

    const int tid = threadIdx.x;
    const int ox = tid & 31;  // output group: features [4*ox, 4*ox+4)
    const int my = tid >> 5;  // node group:   nodes    [4*my, 4*my+4)

    // Load both weight matrices into shared memory (once per block)
    {
        const float4* wl4 = (const float4*)Wl;
        const float4* wr4 = (const float4*)Wr;
        float4* wls4 = (float4*)Wls;
        float4* wrs4 = (float4*)Wrs;
        for (int i = tid; i < C * C / 4; i += LAYER_THREADS) {
            wls4[i] = wl4[i];
            wrs4[i] = wr4[i];
        }
    }

    float4 b4;
    float wfc_reg[4];
    float bfc0 = 0.f;
    if (FC) {
        wfc_reg[0] = Wfc[ox * 4 + 0];
        wfc_reg[1] = Wfc[ox * 4 + 1];
        wfc_reg[2] = Wfc[ox * 4 + 2];
        wfc_reg[3] = Wfc[ox * 4 + 3];
        bfc0 = bfc[0];
    }
    b4 = ((const float4*)bias)[ox];

    const int n_tiles = n_nodes / TILE_NODES;

    for (int tile = blockIdx.x; tile < n_tiles; tile += gridDim.x) {
        const int base = tile * TILE_NODES;
        __syncthreads();  // previous iteration done reading smem / weights loaded

        // Load this tile's inputs: normalize agg by degree on the fly
        for (int q = tid; q < TILE_NODES * C / 4; q += LAYER_THREADS) {
            int node = q >> 5;  // 32 float4s per row
            int k4 = q & 31;
            int gn = base + node;
            float dg = deg[gn];
            float r = 1.0f / fmaxf(dg, 1.0f);
            float4 a = ((const float4*)(agg_sum + (size_t)gn * C))[k4];
            a.x *= r; a.y *= r; a.z *= r; a.w *= r;
            ((float4*)as_)[q] = a;
            ((float4*)xs_)[q] = ((const float4*)(in_feat + (size_t)gn * C))[k4];
        }
        __syncthreads();

        float acc[4][4];
#pragma unroll
        for (int t = 0; t < 4; ++t)
#pragma unroll
            for (int j = 0; j < 4; ++j) acc[t][j] = 0.f;

#pragma unroll 8
        for (int k = 0; k < C; ++k) {
            float4 wl = *(const float4*)(Wls + k * C + ox * 4);
            float4 wr = *(const float4*)(Wrs + k * C + ox * 4);
#pragma unroll
            for (int t = 0; t < 4; ++t) {
                float ag = as_[(my * 4 + t) * C + k];
                float xv = xs_[(my * 4 + t) * C + k];
                acc[t][0] = fmaf(ag, wl.x, fmaf(xv, wr.x, acc[t][0]));
                acc[t][1] = fmaf(ag, wl.y, fmaf(xv, wr.y, acc[t][1]));
                acc[t][2] = fmaf(ag, wl.z, fmaf(xv, wr.z, acc[t][2]));
                acc[t][3] = fmaf(ag, wl.w, fmaf(xv, wr.w, acc[t][3]));
            }
        }

        if (!FC) {
#pragma unroll
            for (int t = 0; t < 4; ++t) {
                float4 hv;
                hv.x = fmaxf(acc[t][0] + b4.x, 0.f);
                hv.y = fmaxf(acc[t][1] + b4.y, 0.f);
                hv.z = fmaxf(acc[t][2] + b4.z, 0.f);
                hv.w = fmaxf(acc[t][3] + b4.w, 0.f);
                int row = base + my * 4 + t;
                ((float4*)(out_h + (size_t)row * C))[ox] = hv;
            }
        } else {
#pragma unroll
            for (int t = 0; t < 4; ++t) {
                float h0 = fmaxf(acc[t][0] + b4.x, 0.f);
                float h1v = fmaxf(acc[t][1] + b4.y, 0.f);
                float h2v = fmaxf(acc[t][2] + b4.z, 0.f);
                float h3v = fmaxf(acc[t][3] + b4.w, 0.f);
                float p = h0 * wfc_reg[0] + h1v * wfc_reg[1] +
                          h2v * wfc_reg[2] + h3v * wfc_reg[3];
                // warp covers all 32 output groups (ox = lane) -> full dot
#pragma unroll
                for (int off = 16; off > 0; off >>= 1)
                    p += __shfl_xor_sync(0xffffffffu, p, off);
                if (ox == 0) {
                    float z = p + bfc0;
                    out_fc[base + my * 4 + t] = 1.0f / (1.0f + expf(-z));
                }
            }
        }
    }
}

// ---------------------------------------------------------------------------
extern "C" void kernel_launch(void* const* d_in, const int* in_sizes, int n_in,
                              void* d_out, int out_size) {
    const float* x = (const float*)d_in[0];
    const int* ei = (const int*)d_in[1];  // JAX x64 disabled -> int32
    const float* W1l = (const float*)d_in[2];
    const float* W1r = (const float*)d_in[3];
    const float* b1 = (const float*)d_in[4];
    const float* W2l = (const float*)d_in[5];
    const float* W2r = (const float*)d_in[6];
    const float* b2 = (const float*)d_in[7];
    const float* Wfc = (const float*)d_in[8];
    const float* bfc = (const float*)d_in[9];
    float* out = (float*)d_out;

    const int E = in_sizes[1] / 2;
    const int* src = ei;
    const int* dst = ei + E;

    float *agg, *deg, *h1;
    cudaGetSymbolAddress((void**)&agg, g_agg);
    cudaGetSymbolAddress((void**)&deg, g_deg);
    cudaGetSymbolAddress((void**)&h1, g_h1);

    cudaFuncSetAttribute(layer_kernel<false>,
                         cudaFuncAttributeMaxDynamicSharedMemorySize, SMEM_BYTES);
    cudaFuncSetAttribute(layer_kernel<true>,
                         cudaFuncAttributeMaxDynamicSharedMemorySize, SMEM_BYTES);

    const size_t n4 = (size_t)N_NODES * C / 4;
    const int scatter_blocks = (E + 7) / 8;  // 8 warps (edges) per 256-thr block

    // Layer 1
    zero_kernel<<<2048, 256>>>(agg, n4);
    zero_scalar_kernel<<<(N_NODES + 255) / 256, 256>>>(deg, N_NODES);
    scatter_kernel<<<scatter_blocks, 256>>>(x, src, dst, agg, deg, E, 1);
    layer_kernel<false><<<148, LAYER_THREADS, SMEM_BYTES>>>(
        x, agg, deg, W1l, W1r, b1, h1, nullptr, nullptr, nullptr, N_NODES);

    // Layer 2 (+ fused FC head)
    zero_kernel<<<2048, 256>>>(agg, n4);
    scatter_kernel<<<scatter_blocks, 256>>>(h1, src, dst, agg, deg, E, 0);
    layer_kernel<true><<<148, LAYER_THREADS, SMEM_BYTES>>>(
        h1, agg, deg, W2l, W2r, b2, nullptr, Wfc, bfc, out, N_NODES);
}

// round 5
// speedup vs baseline: 1.5240x; 1.5240x over previous
#include <cuda_runtime.h>
#include <math.h>

#define N_NODES 100000
#define C 128
#define TILE_NODES 64
#define LAYER_THREADS 512
// smem: Wl(128*128) + Wr(128*128) + agg_tile(64*128) + x_tile(64*128) floats
#define SMEM_FLOATS (2 * C * C + 2 * TILE_NODES * C)
#define SMEM_BYTES (SMEM_FLOATS * 4)  // 192 KB

// Scratch (allocation-free rule: __device__ globals)
__device__ float g_agg[(size_t)N_NODES * C];
__device__ float g_h1[(size_t)N_NODES * C];
__device__ float g_deg[N_NODES];

// ---------------------------------------------------------------------------
// Zero agg (float4 strided) and deg together
// ---------------------------------------------------------------------------
__global__ void zero_kernel(float* __restrict__ agg, float* __restrict__ deg,
                            size_t n4, int ndeg) {
    float4* p4 = (float4*)agg;
    float4 z = make_float4(0.f, 0.f, 0.f, 0.f);
    size_t i0 = (size_t)blockIdx.x * blockDim.x + threadIdx.x;
    for (size_t i = i0; i < n4; i += (size_t)gridDim.x * blockDim.x) p4[i] = z;
    if (deg)
        for (size_t i = i0; i < (size_t)ndeg; i += (size_t)gridDim.x * blockDim.x)
            deg[i] = 0.f;
}

// deg -> 1/max(deg,1)
__global__ void rcp_deg_kernel(float* __restrict__ deg, int n) {
    int i = blockIdx.x * blockDim.x + threadIdx.x;
    if (i < n) deg[i] = 1.0f / fmaxf(deg[i], 1.0f);
}

// ---------------------------------------------------------------------------
// Scatter: accum[dst] += feat[src], deg[dst] += 1. One warp per edge.
// Lane l owns floats [4l, 4l+4): a single red.global.add.v4.f32 per lane.
// ---------------------------------------------------------------------------
__global__ void scatter_kernel(const float* __restrict__ feat,
                               const int* __restrict__ src,
                               const int* __restrict__ dst,
                               float* __restrict__ accum,
                               float* __restrict__ deg,
                               int E, int add_deg) {
    int warp = (blockIdx.x * blockDim.x + threadIdx.x) >> 5;
    int lane = threadIdx.x & 31;
    if (warp >= E) return;
    int s = src[warp];
    int d = dst[warp];
    float4 v = ((const float4*)(feat + (size_t)s * C))[lane];
    float* a = accum + (size_t)d * C + lane * 4;
    asm volatile("red.global.add.v4.f32 [%0], {%1, %2, %3, %4};" ::
                     "l"(a), "f"(v.x), "f"(v.y), "f"(v.z), "f"(v.w)
                 : "memory");
    if (add_deg && lane == 0) atomicAdd(deg + d, 1.0f);
}

// ---------------------------------------------------------------------------
// Fused SAGE layer:
//   h[i] = relu( (agg_sum[i]*invdeg[i]) @ Wl + in[i] @ Wr + b )
// If FC: instead of storing h, compute sigmoid(h @ Wfc + bfc) -> out_fc[i].
//
// Persistent blocks. 512 threads, 64-node tiles, 4 nodes x 4 outs per thread.
// Both weight matrices resident in shared memory for the whole kernel.
// Mainloop consumes K in float4 chunks: 16 LDS.128 per 128 FFMA.
// ---------------------------------------------------------------------------
template <bool FC>
__global__ void __launch_bounds__(LAYER_THREADS, 1)
layer_kernel(const float* __restrict__ in_feat,
             const float* __restrict__ agg_sum,
             const float* __restrict__ invdeg,
             const float* __restrict__ Wl,
             const float* __restrict__ Wr,
             const float* __restrict__ bias,
             float* __restrict__ out_h,
             const float* __restrict__ Wfc,
             const float* __restrict__ bfc,
             float* __restrict__ out_fc,
             int n_nodes) {
    extern __shared__ float smem[];
    float* Wls = smem;                 // [128][128]
    float* Wrs = Wls + C * C;          // [128][128]
    float* as_ = Wrs + C * C;          // [64][128] normalized agg
    float* xs_ = as_ + TILE_NODES * C; // [64][128] input feats

    const int tid = threadIdx.x;
    const int ox = tid & 31;  // output group: features [4*ox, 4*ox+4)
    const int my = tid >> 5;  // node group:   nodes    [4*my, 4*my+4)  (16 groups)

    // Load both weight matrices into shared memory (once per block)
    {
        const float4* wl4 = (const float4*)Wl;
        const float4* wr4 = (const float4*)Wr;
        float4* wls4 = (float4*)Wls;
        float4* wrs4 = (float4*)Wrs;
        for (int i = tid; i < C * C / 4; i += LAYER_THREADS) {
            wls4[i] = wl4[i];
            wrs4[i] = wr4[i];
        }
    }

    float4 b4 = ((const float4*)bias)[ox];
    float wfc_reg[4];
    float bfc0 = 0.f;
    if (FC) {
        wfc_reg[0] = Wfc[ox * 4 + 0];
        wfc_reg[1] = Wfc[ox * 4 + 1];
        wfc_reg[2] = Wfc[ox * 4 + 2];
        wfc_reg[3] = Wfc[ox * 4 + 3];
        bfc0 = bfc[0];
    }

    const int n_tiles = (n_nodes + TILE_NODES - 1) / TILE_NODES;

    for (int tile = blockIdx.x; tile < n_tiles; tile += gridDim.x) {
        const int base = tile * TILE_NODES;
        __syncthreads();  // previous iteration done reading smem

        // Load this tile's inputs; normalize agg by invdeg on the fly.
        // 64*32 = 2048 float4 slots, 4 per thread.
        for (int q = tid; q < TILE_NODES * C / 4; q += LAYER_THREADS) {
            int node = q >> 5;  // 32 float4s per row
            int k4 = q & 31;
            int gn = base + node;
            float4 a, xv;
            if (gn < n_nodes) {
                float r = invdeg[gn];
                a = ((const float4*)(agg_sum + (size_t)gn * C))[k4];
                a.x *= r; a.y *= r; a.z *= r; a.w *= r;
                xv = ((const float4*)(in_feat + (size_t)gn * C))[k4];
            } else {
                a = make_float4(0.f, 0.f, 0.f, 0.f);
                xv = a;
            }
            ((float4*)as_)[q] = a;
            ((float4*)xs_)[q] = xv;
        }
        __syncthreads();

        float acc[4][4];
#pragma unroll
        for (int t = 0; t < 4; ++t)
#pragma unroll
            for (int j = 0; j < 4; ++j) acc[t][j] = 0.f;

#pragma unroll 2
        for (int k4 = 0; k4 < C / 4; ++k4) {
            float4 wl0 = *(const float4*)(Wls + (k4 * 4 + 0) * C + ox * 4);
            float4 wl1 = *(const float4*)(Wls + (k4 * 4 + 1) * C + ox * 4);
            float4 wl2 = *(const float4*)(Wls + (k4 * 4 + 2) * C + ox * 4);
            float4 wl3 = *(const float4*)(Wls + (k4 * 4 + 3) * C + ox * 4);
            float4 wr0 = *(const float4*)(Wrs + (k4 * 4 + 0) * C + ox * 4);
            float4 wr1 = *(const float4*)(Wrs + (k4 * 4 + 1) * C + ox * 4);
            float4 wr2 = *(const float4*)(Wrs + (k4 * 4 + 2) * C + ox * 4);
            float4 wr3 = *(const float4*)(Wrs + (k4 * 4 + 3) * C + ox * 4);
#pragma unroll
            for (int t = 0; t < 4; ++t) {
                const int row = my * 4 + t;
                float4 ag = *(const float4*)(as_ + row * C + k4 * 4);
                float4 xv = *(const float4*)(xs_ + row * C + k4 * 4);
                acc[t][0] = fmaf(ag.x, wl0.x, acc[t][0]);
                acc[t][1] = fmaf(ag.x, wl0.y, acc[t][1]);
                acc[t][2] = fmaf(ag.x, wl0.z, acc[t][2]);
                acc[t][3] = fmaf(ag.x, wl0.w, acc[t][3]);
                acc[t][0] = fmaf(xv.x, wr0.x, acc[t][0]);
                acc[t][1] = fmaf(xv.x, wr0.y, acc[t][1]);
                acc[t][2] = fmaf(xv.x, wr0.z, acc[t][2]);
                acc[t][3] = fmaf(xv.x, wr0.w, acc[t][3]);
                acc[t][0] = fmaf(ag.y, wl1.x, acc[t][0]);
                acc[t][1] = fmaf(ag.y, wl1.y, acc[t][1]);
                acc[t][2] = fmaf(ag.y, wl1.z, acc[t][2]);
                acc[t][3] = fmaf(ag.y, wl1.w, acc[t][3]);
                acc[t][0] = fmaf(xv.y, wr1.x, acc[t][0]);
                acc[t][1] = fmaf(xv.y, wr1.y, acc[t][1]);
                acc[t][2] = fmaf(xv.y, wr1.z, acc[t][2]);
                acc[t][3] = fmaf(xv.y, wr1.w, acc[t][3]);
                acc[t][0] = fmaf(ag.z, wl2.x, acc[t][0]);
                acc[t][1] = fmaf(ag.z, wl2.y, acc[t][1]);
                acc[t][2] = fmaf(ag.z, wl2.z, acc[t][2]);
                acc[t][3] = fmaf(ag.z, wl2.w, acc[t][3]);
                acc[t][0] = fmaf(xv.z, wr2.x, acc[t][0]);
                acc[t][1] = fmaf(xv.z, wr2.y, acc[t][1]);
                acc[t][2] = fmaf(xv.z, wr2.z, acc[t][2]);
                acc[t][3] = fmaf(xv.z, wr2.w, acc[t][3]);
                acc[t][0] = fmaf(ag.w, wl3.x, acc[t][0]);
                acc[t][1] = fmaf(ag.w, wl3.y, acc[t][1]);
                acc[t][2] = fmaf(ag.w, wl3.z, acc[t][2]);
                acc[t][3] = fmaf(ag.w, wl3.w, acc[t][3]);
                acc[t][0] = fmaf(xv.w, wr3.x, acc[t][0]);
                acc[t][1] = fmaf(xv.w, wr3.y, acc[t][1]);
                acc[t][2] = fmaf(xv.w, wr3.z, acc[t][2]);
                acc[t][3] = fmaf(xv.w, wr3.w, acc[t][3]);
            }
        }

        if (!FC) {
#pragma unroll
            for (int t = 0; t < 4; ++t) {
                int row = base + my * 4 + t;
                if (row < n_nodes) {
                    float4 hv;
                    hv.x = fmaxf(acc[t][0] + b4.x, 0.f);
                    hv.y = fmaxf(acc[t][1] + b4.y, 0.f);
                    hv.z = fmaxf(acc[t][2] + b4.z, 0.f);
                    hv.w = fmaxf(acc[t][3] + b4.w, 0.f);
                    ((float4*)(out_h + (size_t)row * C))[ox] = hv;
                }
            }
        } else {
#pragma unroll
            for (int t = 0; t < 4; ++t) {
                float h0 = fmaxf(acc[t][0] + b4.x, 0.f);
                float h1v = fmaxf(acc[t][1] + b4.y, 0.f);
                float h2v = fmaxf(acc[t][2] + b4.z, 0.f);
                float h3v = fmaxf(acc[t][3] + b4.w, 0.f);
                float p = h0 * wfc_reg[0] + h1v * wfc_reg[1] +
                          h2v * wfc_reg[2] + h3v * wfc_reg[3];
#pragma unroll
                for (int off = 16; off > 0; off >>= 1)
                    p += __shfl_xor_sync(0xffffffffu, p, off);
                int row = base + my * 4 + t;
                if (ox == 0 && row < n_nodes) {
                    float z = p + bfc0;
                    out_fc[row] = 1.0f / (1.0f + expf(-z));
                }
            }
        }
    }
}

// ---------------------------------------------------------------------------
extern "C" void kernel_launch(void* const* d_in, const int* in_sizes, int n_in,
                              void* d_out, int out_size) {
    const float* x = (const float*)d_in[0];
    const int* ei = (const int*)d_in[1];  // int32 (JAX x64 disabled)
    const float* W1l = (const float*)d_in[2];
    const float* W1r = (const float*)d_in[3];
    const float* b1 = (const float*)d_in[4];
    const float* W2l = (const float*)d_in[5];
    const float* W2r = (const float*)d_in[6];
    const float* b2 = (const float*)d_in[7];
    const float* Wfc = (const float*)d_in[8];
    const float* bfc = (const float*)d_in[9];
    float* out = (float*)d_out;

    const int E = in_sizes[1] / 2;
    const int* src = ei;
    const int* dst = ei + E;

    float *agg, *deg, *h1;
    cudaGetSymbolAddress((void**)&agg, g_agg);
    cudaGetSymbolAddress((void**)&deg, g_deg);
    cudaGetSymbolAddress((void**)&h1, g_h1);

    cudaFuncSetAttribute(layer_kernel<false>,
                         cudaFuncAttributeMaxDynamicSharedMemorySize, SMEM_BYTES);
    cudaFuncSetAttribute(layer_kernel<true>,
                         cudaFuncAttributeMaxDynamicSharedMemorySize, SMEM_BYTES);

    const size_t n4 = (size_t)N_NODES * C / 4;
    const int scatter_blocks = (E + 7) / 8;  // 8 warps (edges) per 256-thr block

    // Layer 1
    zero_kernel<<<2048, 256>>>(agg, deg, n4, N_NODES);
    scatter_kernel<<<scatter_blocks, 256>>>(x, src, dst, agg, deg, E, 1);
    rcp_deg_kernel<<<(N_NODES + 255) / 256, 256>>>(deg, N_NODES);
    layer_kernel<false><<<148, LAYER_THREADS, SMEM_BYTES>>>(
        x, agg, deg, W1l, W1r, b1, h1, nullptr, nullptr, nullptr, N_NODES);

    // Layer 2 (+ fused FC head)
    zero_kernel<<<2048, 256>>>(agg, nullptr, n4, 0);
    scatter_kernel<<<scatter_blocks, 256>>>(h1, src, dst, agg, deg, E, 0);
    layer_kernel<true><<<148, LAYER_THREADS, SMEM_BYTES>>>(
        h1, agg, deg, W2l, W2r, b2, nullptr, Wfc, bfc, out, N_NODES);
}